// round 2
// baseline (speedup 1.0000x reference)
#include <cuda_runtime.h>

#define DTc 0.05f

// global scratch (static device arrays; no allocation)
__device__ float g_s2  [64*256*64];
__device__ float g_xres[64*256*64];
__device__ float g_K   [64*256*16*64];
__device__ float g_kv  [64*256*16];
__device__ float g_s   [64*256*64];
__device__ float g_P   [(size_t)64*256*64*64];

// C(64x64) = [A1] + [A2] + alpha * L(64x64) @ R(64x64), row-major, 256 threads
__device__ __forceinline__ void gemm64(float* __restrict__ C, const float* __restrict__ L,
                                       const float* __restrict__ R, float alpha,
                                       const float* __restrict__ A1, const float* __restrict__ A2)
{
    const int tid = threadIdx.x;
    const int c0 = (tid & 15) * 4, r0 = (tid >> 4) * 4;
    float acc[4][4];
#pragma unroll
    for (int r = 0; r < 4; r++) { acc[r][0]=0.f; acc[r][1]=0.f; acc[r][2]=0.f; acc[r][3]=0.f; }
#pragma unroll 4
    for (int jj = 0; jj < 16; jj++) {
        float4 lv[4], rv[4];
#pragma unroll
        for (int r = 0; r < 4; r++) lv[r] = *(const float4*)(L + (r0+r)*64 + jj*4);
#pragma unroll
        for (int q = 0; q < 4; q++) rv[q] = *(const float4*)(R + (jj*4+q)*64 + c0);
#pragma unroll
        for (int r = 0; r < 4; r++) {
            const float* lp = (const float*)&lv[r];
#pragma unroll
            for (int q = 0; q < 4; q++) {
                const float l = lp[q];
                acc[r][0] = fmaf(l, rv[q].x, acc[r][0]);
                acc[r][1] = fmaf(l, rv[q].y, acc[r][1]);
                acc[r][2] = fmaf(l, rv[q].z, acc[r][2]);
                acc[r][3] = fmaf(l, rv[q].w, acc[r][3]);
            }
        }
    }
#pragma unroll
    for (int r = 0; r < 4; r++) {
        const int base = (r0+r)*64 + c0;
#pragma unroll
        for (int c = 0; c < 4; c++) {
            float v = alpha * acc[r][c];
            if (A1) v += A1[base+c];
            if (A2) v += A2[base+c];
            C[base+c] = v;
        }
    }
}

// C(64x16) = [A1] + alpha * L(64x64) @ R(64x16); thread = 4 rows x 1 col
__device__ __forceinline__ void gemm64x16(float* __restrict__ C, const float* __restrict__ L,
                                          const float* __restrict__ R, float alpha,
                                          const float* __restrict__ A1)
{
    const int tid = threadIdx.x;
    const int c = tid & 15, r0 = (tid >> 4) * 4;
    float acc[4] = {0.f,0.f,0.f,0.f};
#pragma unroll 4
    for (int jj = 0; jj < 16; jj++) {
        float4 lv[4];
#pragma unroll
        for (int r = 0; r < 4; r++) lv[r] = *(const float4*)(L + (r0+r)*64 + jj*4);
#pragma unroll
        for (int q = 0; q < 4; q++) {
            const float rv = R[(jj*4+q)*16 + c];
            acc[0] = fmaf(((const float*)&lv[0])[q], rv, acc[0]);
            acc[1] = fmaf(((const float*)&lv[1])[q], rv, acc[1]);
            acc[2] = fmaf(((const float*)&lv[2])[q], rv, acc[2]);
            acc[3] = fmaf(((const float*)&lv[3])[q], rv, acc[3]);
        }
    }
#pragma unroll
    for (int r = 0; r < 4; r++) {
        float v = alpha * acc[r];
        if (A1) v += A1[(r0+r)*16 + c];
        C[(r0+r)*16 + c] = v;
    }
}

// C(64x64) = A1 + L(64x16) @ R(16x64)
__device__ __forceinline__ void gemmPn(float* __restrict__ C, const float* __restrict__ L,
                                       const float* __restrict__ R, const float* __restrict__ A1)
{
    const int tid = threadIdx.x;
    const int c0 = (tid & 15) * 4, r0 = (tid >> 4) * 4;
    float acc[4][4];
#pragma unroll
    for (int r = 0; r < 4; r++) { acc[r][0]=0.f; acc[r][1]=0.f; acc[r][2]=0.f; acc[r][3]=0.f; }
#pragma unroll
    for (int jj = 0; jj < 4; jj++) {
        float4 lv[4], rv[4];
#pragma unroll
        for (int r = 0; r < 4; r++) lv[r] = *(const float4*)(L + (r0+r)*16 + jj*4);
#pragma unroll
        for (int q = 0; q < 4; q++) rv[q] = *(const float4*)(R + (jj*4+q)*64 + c0);
#pragma unroll
        for (int r = 0; r < 4; r++) {
            const float* lp = (const float*)&lv[r];
#pragma unroll
            for (int q = 0; q < 4; q++) {
                const float l = lp[q];
                acc[r][0] = fmaf(l, rv[q].x, acc[r][0]);
                acc[r][1] = fmaf(l, rv[q].y, acc[r][1]);
                acc[r][2] = fmaf(l, rv[q].z, acc[r][2]);
                acc[r][3] = fmaf(l, rv[q].w, acc[r][3]);
            }
        }
    }
#pragma unroll
    for (int r = 0; r < 4; r++) {
        const int base = (r0+r)*64 + c0;
#pragma unroll
        for (int c = 0; c < 4; c++) C[base+c] = A1[base+c] + acc[r][c];
    }
}

__global__ void __launch_bounds__(256, 1) mpc_kernel(
    const float* __restrict__ x0_in, const float* __restrict__ x_in,
    const float* __restrict__ u_in,  const float* __restrict__ lmd_in,
    const float* __restrict__ A_in,  const float* __restrict__ Bm_in,
    const float* __restrict__ Qx_in, const float* __restrict__ R_in,
    const float* __restrict__ Vf_in, const float* __restrict__ xref_in,
    float* __restrict__ out)
{
    extern __shared__ float sh[];
    float* sA   = sh;           float* sAT  = sA+4096;   float* sQx = sAT+4096;
    float* sP   = sQx+4096;     float* sM1  = sP+4096;   float* sM2 = sM1+4096;
    float* sBm  = sM2+4096;     float* sBmT = sBm+1024;  float* sPFu= sBmT+1024;
    float* sW   = sPFu+1024;    float* sQxu = sW+1024;   float* sK  = sQxu+1024;
    float* sR   = sK+1024;      float* sGJ  = sR+256;    float* sInv= sGJ+528;
    float* vxref= sInv+272;
    float* vrN  = vxref+64; float* vx0r = vrN+64;  float* vs2  = vx0r+64;
    float* vxres= vs2+64;   float* vsv  = vxres+64;float* vxn  = vsv+64;
    float* vxn1 = vxn+64;   float* vlmd0= vxn1+64; float* vlmd1= vlmd0+64;
    float* vq   = vlmd1+64; float* vxmr = vq+64;   float* vrx  = vxmr+64;
    float* vv   = vrx+64;   float* vq2  = vv+64;   float* vlx  = vq2+64;
    float* vdx  = vlx+64;   float* vdxn = vdx+64;
    float* vu   = vdxn+64;  float* vru  = vu+16;   float* vlu  = vru+16;
    float* vkk  = vlu+16;   float* vdu  = vkk+16;  float* sfac = vdu+16;

    const int tid = threadIdx.x, b = blockIdx.x;
    float* xw = out;
    float* uw = out + 65*256*64;
    float* lw = uw  + 64*256*16;

    for (int e = tid; e < 4096; e += 256) {
        float a = A_in[e];
        sA[e] = a; sQx[e] = Qx_in[e];
        int i = e >> 6, j = e & 63;
        sAT[j*64+i] = a;
    }
    for (int e = tid; e < 1024; e += 256) {
        float v = Bm_in[e]; sBm[e] = v;
        int j = e >> 4, i = e & 15;
        sBmT[i*64+j] = v;
    }
    sR[tid] = R_in[tid];
    if (tid < 64) vxref[tid] = xref_in[tid];
    for (int e = tid; e < 65*64; e += 256) {
        int n = e >> 6, i = e & 63;
        int idx = (n*256 + b)*64 + i;
        xw[idx] = x_in[idx]; lw[idx] = lmd_in[idx];
    }
    for (int e = tid; e < 64*16; e += 256) {
        int n = e >> 4, i = e & 15;
        int idx = (n*256 + b)*16 + i;
        uw[idx] = u_in[idx];
    }
    __syncthreads();

    for (int iter = 0; iter < 2; iter++) {
        // terminal: P_N = Vf, rN = Vf(x_N-xref) - lmd_N, s_N = rN
        for (int e = tid; e < 4096; e += 256) sP[e] = Vf_in[e];
        if (tid < 64) {
            vxn[tid]  = xw[(64*256 + b)*64 + tid];
            vx0r[tid] = xw[b*64 + tid] - x0_in[b*64 + tid];
        }
        __syncthreads();
        if (tid < 64) {
            const int j = tid; float acc = 0.f;
#pragma unroll 8
            for (int i = 0; i < 64; i++) acc = fmaf(sP[i*64+j], vxn[i]-vxref[i], acc);
            float r = acc - lw[(64*256 + b)*64 + j];
            vrN[j] = r; vsv[j] = r;
        }
        __syncthreads();

        // ---------------- backward Riccati ----------------
        for (int n = 63; n >= 0; n--) {
            const int ofs = n*256 + b;
            if (tid < 64) {
                vxn[tid]   = xw[ofs*64 + tid];
                vxn1[tid]  = xw[(ofs+256)*64 + tid];
                vlmd0[tid] = lw[ofs*64 + tid];
                vlmd1[tid] = lw[(ofs+256)*64 + tid];
            } else if (tid < 80) {
                vu[tid-64] = uw[ofs*16 + tid-64];
            }
            __syncthreads();
            if (tid < 64) {
                const int j = tid; float z = 0.f;
#pragma unroll 8
                for (int i = 0; i < 64; i++) z = fmaf(sAT[i*64+j], vxn[i], z);
#pragma unroll
                for (int i = 0; i < 16; i++) z = fmaf(sBmT[i*64+j], vu[i], z);
                float t = tanhf(z), s2 = 1.f - t*t;
                vs2[j] = s2;
                float xr = vxn[j] + DTc*t - vxn1[j];
                vxres[j] = xr;
                vq[j]   = s2 * vlmd1[j];
                vxmr[j] = vxn[j] - vxref[j];
                g_s2[ofs*64+j] = s2; g_xres[ofs*64+j] = xr;
            }
            __syncthreads();
            if (tid < 64) {
                const int j = tid; float a1 = 0.f, a2 = 0.f;
#pragma unroll 8
                for (int i = 0; i < 64; i++) {
                    a1 = fmaf(sQx[i*64+j], vxmr[i], a1);
                    a2 = fmaf(sA[i*64+j],  vq[i],   a2);
                }
                vrx[j] = a1 + vlmd1[j] + DTc*a2 - vlmd0[j];
            } else if (tid < 80) {
                const int j = tid - 64; float a1 = 0.f, a2 = 0.f;
#pragma unroll
                for (int i = 0; i < 16; i++) a1 = fmaf(sR[i*16+j], vu[i], a1);
#pragma unroll 8
                for (int i = 0; i < 64; i++) a2 = fmaf(sBm[i*16+j], vq[i], a2);
                vru[j] = a1 + DTc*a2;
            }
            for (int e = tid; e < 4096; e += 256) sM2[e] = sP[e] * vs2[e & 63];   // Y
            __syncthreads();
            gemm64(sM1, sM2, sA, DTc, sP, 0);          // PFx = P + DT*Y@A
            gemm64x16(sPFu, sM2, sBm, DTc, 0);         // PFu = DT*Y@Bm
            __syncthreads();
            for (int e = tid; e < 4096; e += 256) sM2[e] = vs2[e >> 6] * sM1[e];  // Z
            for (int e = tid; e < 1024; e += 256) sW[e]  = vs2[e >> 4] * sPFu[e]; // W
            if (tid < 64) {
                const int j = tid; float acc = 0.f;
#pragma unroll 8
                for (int i = 0; i < 64; i++) acc = fmaf(sP[i*64+j], vxres[i], acc);
                float vv_ = acc + vsv[j];
                vv[j] = vv_; vq2[j] = vs2[j] * vv_;
            }
            __syncthreads();
            gemm64(sM1, sAT, sM2, DTc, sQx, sM1);      // Qxx = Qx + PFx + DT*AT@Z
            {
                const int i = tid >> 4, k = tid & 15; float acc = 0.f;
#pragma unroll 8
                for (int j = 0; j < 64; j++) acc = fmaf(sBmT[i*64+j], sW[j*16+k], acc);
                sGJ[i*33+k]    = sR[i*16+k] + DTc*acc; // Quu
                sGJ[i*33+16+k] = (i == k) ? 1.f : 0.f;
            }
            gemm64x16(sQxu, sAT, sW, DTc, sPFu);       // Qxu = PFu + DT*AT@W
            if (tid < 64) {
                const int j = tid; float acc = 0.f;
#pragma unroll 8
                for (int i = 0; i < 64; i++) acc = fmaf(sA[i*64+j], vq2[i], acc);
                vlx[j] = vrx[j] + vv[j] + DTc*acc;
            } else if (tid < 80) {
                const int j = tid - 64; float acc = 0.f;
#pragma unroll 8
                for (int i = 0; i < 64; i++) acc = fmaf(sBm[i*16+j], vq2[i], acc);
                vlu[j] = vru[j] + DTc*acc;
            }
            __syncthreads();
            // Gauss-Jordan inverse of Quu (SPD)
            for (int p = 0; p < 16; p++) {
                if (tid < 16) sfac[tid] = sGJ[tid*33+p];
                __syncthreads();
                const float pinv = 1.f / sfac[p];
                if (tid < 32) sGJ[p*33+tid] *= pinv;
                __syncthreads();
                for (int e = tid; e < 512; e += 256) {
                    int r = e >> 5, c = e & 31;
                    if (r != p) sGJ[r*33+c] -= sfac[r] * sGJ[p*33+c];
                }
                __syncthreads();
            }
            { int r = tid >> 4, c = tid & 15; sInv[r*17+c] = sGJ[r*33+16+c]; }
            __syncthreads();
            // K = -Inv @ Qxu^T, k = -Inv @ lu
            {
                const int i = tid & 15, m0 = (tid >> 4) * 4;
                float a0=0.f,a1=0.f,a2=0.f,a3=0.f;
#pragma unroll
                for (int j = 0; j < 16; j++) {
                    const float iv = sInv[i*17+j];
                    a0 = fmaf(iv, sQxu[(m0+0)*16+j], a0);
                    a1 = fmaf(iv, sQxu[(m0+1)*16+j], a1);
                    a2 = fmaf(iv, sQxu[(m0+2)*16+j], a2);
                    a3 = fmaf(iv, sQxu[(m0+3)*16+j], a3);
                }
                sK[i*64+m0]=-a0; sK[i*64+m0+1]=-a1; sK[i*64+m0+2]=-a2; sK[i*64+m0+3]=-a3;
            }
            if (tid < 16) {
                float a = 0.f;
#pragma unroll
                for (int j = 0; j < 16; j++) a = fmaf(sInv[tid*17+j], vlu[j], a);
                vkk[tid] = -a;
            }
            __syncthreads();
            gemmPn(sM2, sQxu, sK, sM1);                // Pn = Qxx + Qxu@K
            __syncthreads();
            // symmetrize (skewed, conflict-free), sn = lx + Qxu@k
            {
                const int i = tid & 63, g = tid >> 6;
#pragma unroll
                for (int rep = 0; rep < 16; rep++) {
                    int j = (g*16 + rep + i) & 63;
                    sP[i*64+j] = 0.5f * (sM2[i*64+j] + sM2[j*64+i]);
                }
            }
            if (tid < 64) {
                const int j = tid; float a = vlx[j];
#pragma unroll
                for (int i = 0; i < 16; i++) a = fmaf(sQxu[j*16+i], vkk[i], a);
                vsv[j] = a; g_s[ofs*64+j] = a;
            } else if (tid < 80) {
                g_kv[ofs*16 + tid-64] = vkk[tid-64];
            }
            __syncthreads();
            for (int e = tid; e < 1024; e += 256)
                ((float4*)(g_P + (size_t)ofs*4096))[e] = ((const float4*)sP)[e];
            ((float4*)(g_K + (size_t)ofs*1024))[tid] = ((const float4*)sK)[tid];
            __syncthreads();
        }

        // ---------------- forward rollout ----------------
        if (tid < 64) vdx[tid] = -vx0r[tid];
        __syncthreads();
        for (int n = 0; n < 64; n++) {
            const int ofs = n*256 + b;
            for (int e = tid; e < 1024; e += 256)
                ((float4*)sM1)[e] = ((const float4*)(g_P + (size_t)ofs*4096))[e];
            ((float4*)sK)[tid] = ((const float4*)(g_K + (size_t)ofs*1024))[tid];
            if (tid < 64) { vs2[tid] = g_s2[ofs*64+tid]; vxres[tid] = g_xres[ofs*64+tid]; }
            __syncthreads();
            if (tid < 16) {
                float a = g_kv[ofs*16 + tid];
#pragma unroll 8
                for (int m = 0; m < 64; m++) {
                    int mm = (tid*4 + m) & 63;
                    a = fmaf(sK[tid*64+mm], vdx[mm], a);
                }
                vdu[tid] = a;
            }
            __syncthreads();
            if (tid < 64) {
                const int j = tid; float adx = 0.f, pdx = 0.f, bdu = 0.f;
#pragma unroll 8
                for (int i = 0; i < 64; i++) {
                    adx = fmaf(sAT[i*64+j], vdx[i], adx);
                    pdx = fmaf(sM1[i*64+j], vdx[i], pdx);
                }
#pragma unroll
                for (int i = 0; i < 16; i++) bdu = fmaf(sBmT[i*64+j], vdu[i], bdu);
                vdxn[j] = vdx[j] + DTc*vs2[j]*(adx + bdu) + vxres[j];
                const int idx = ofs*64 + j;
                xw[idx] += vdx[j];
                lw[idx] += pdx + g_s[ofs*64+j];
            } else if (tid < 80) {
                uw[ofs*16 + tid-64] += vdu[tid-64];
            }
            __syncthreads();
            if (tid < 64) vdx[tid] = vdxn[tid];
            __syncthreads();
        }
        // terminal: dlmd_N = Vf dxN + rN
        for (int e = tid; e < 4096; e += 256) sM1[e] = Vf_in[e];
        __syncthreads();
        if (tid < 64) {
            const int j = tid; float p = 0.f;
#pragma unroll 8
            for (int i = 0; i < 64; i++) p = fmaf(sM1[i*64+j], vdx[i], p);
            const int idx = (64*256 + b)*64 + j;
            xw[idx] += vdx[j];
            lw[idx] += p + vrN[j];
        }
        __syncthreads();
    }
}

extern "C" void kernel_launch(void* const* d_in, const int* in_sizes, int n_in,
                              void* d_out, int out_size) {
    const float* x0   = (const float*)d_in[0];
    const float* x    = (const float*)d_in[1];
    const float* u    = (const float*)d_in[2];
    const float* lmd  = (const float*)d_in[3];
    const float* A    = (const float*)d_in[4];
    const float* Bm   = (const float*)d_in[5];
    const float* Qx   = (const float*)d_in[6];
    const float* R    = (const float*)d_in[7];
    const float* Vf   = (const float*)d_in[8];
    const float* xref = (const float*)d_in[9];
    cudaFuncSetAttribute(mpc_kernel, cudaFuncAttributeMaxDynamicSharedMemorySize, 135168);
    mpc_kernel<<<256, 256, 132096>>>(x0, x, u, lmd, A, Bm, Qx, R, Vf, xref, (float*)d_out);
}